// round 8
// baseline (speedup 1.0000x reference)
#include <cuda_runtime.h>
#include <cstdint>
#include <cstring>
#include <vector>
#include <algorithm>

// ---------------------------------------------------------------------------
// CLOPLayer: out[b,c,i] = x[b,c,idx[i]], idx fixed (JAX threefry seed 42 +
// sequential neighbor-swap scan), recomputed bit-exact on the HOST each call;
// delivered by one ATS copy kernel (GB300 NVLink-C2C, pageableMemoryAccess=1).
//
// Gather kernel (R8): DIRECT gather, no smem staging. The permutation is
// near-identity (sparse local swaps), so out[i]=x[idx[i]] with consecutive i
// is ~95% coalesced: a warp's loads touch a handful of cache lines, L1 soaks
// the swap stragglers. DRAM traffic = 77MB read + 77MB write = the true
// floor (no halo, unlike the banded smem version). uint16 absolute in-plane
// indices (50176 < 65536). Zero smem, zero syncs, 4.8M threads.
// ---------------------------------------------------------------------------

#define GH 224
#define GW 224
#define HW (GH * GW)          // 50176
#define HW4 (HW / 4)          // 12544
#define NPLANES 384           // 128 * 3
#define HW16 (HW / 8)         // uint4 units of the uint16 idx table

__device__ unsigned short g_idxl[HW];  // absolute in-plane indices (uint16)

// ---- host(ATS) -> device idx copy kernel ----------------------------------
__global__ __launch_bounds__(256)
void write_idx_ats(const uint4* __restrict__ hsrc) {
    int i = blockIdx.x * blockDim.x + threadIdx.x;
    if (i < HW16) {
        reinterpret_cast<uint4*>(g_idxl)[i] = __ldg(&hsrc[i]);
    }
}

// ---- direct gather: grid (HW4/256, NPLANES) --------------------------------
__global__ __launch_bounds__(256)
void clop_direct(const float* __restrict__ x, float* __restrict__ out) {
    const int k = blockIdx.x * 256 + threadIdx.x;      // float4 index in plane
    const int plane = blockIdx.y;
    const float* __restrict__ xp = x + (size_t)plane * HW;

    const ushort4 id = __ldg(reinterpret_cast<const ushort4*>(g_idxl) + k);
    float4 v;
    v.x = __ldg(xp + id.x);
    v.y = __ldg(xp + id.y);
    v.z = __ldg(xp + id.z);
    v.w = __ldg(xp + id.w);
    __stcs(reinterpret_cast<float4*>(out + (size_t)plane * HW) + k, v);
}

// ---------------------------------------------------------------------------
// Host-side exact replication of the JAX RNG pipeline (partitionable threefry)
// ---------------------------------------------------------------------------

static inline uint32_t rotl32(uint32_t x, int d) {
    return (x << d) | (x >> (32 - d));
}

struct TFKey { uint32_t hi, lo; };

static void threefry2x32(uint32_t k0, uint32_t k1, uint32_t x0, uint32_t x1,
                         uint32_t* o0, uint32_t* o1) {
    const uint32_t ks0 = k0, ks1 = k1, ks2 = k0 ^ k1 ^ 0x1BD11BDAu;
    static const int ra[4] = {13, 15, 26, 6};
    static const int rb[4] = {17, 29, 16, 24};
    x0 += ks0; x1 += ks1;
    for (int i = 0; i < 4; i++) { x0 += x1; x1 = rotl32(x1, ra[i]); x1 ^= x0; }
    x0 += ks1; x1 += ks2 + 1u;
    for (int i = 0; i < 4; i++) { x0 += x1; x1 = rotl32(x1, rb[i]); x1 ^= x0; }
    x0 += ks2; x1 += ks0 + 2u;
    for (int i = 0; i < 4; i++) { x0 += x1; x1 = rotl32(x1, ra[i]); x1 ^= x0; }
    x0 += ks0; x1 += ks1 + 3u;
    for (int i = 0; i < 4; i++) { x0 += x1; x1 = rotl32(x1, rb[i]); x1 ^= x0; }
    x0 += ks1; x1 += ks2 + 4u;
    for (int i = 0; i < 4; i++) { x0 += x1; x1 = rotl32(x1, ra[i]); x1 ^= x0; }
    x0 += ks2; x1 += ks0 + 5u;
    *o0 = x0; *o1 = x1;
}

static inline TFKey tf_child(TFKey k, uint32_t j) {
    TFKey r; threefry2x32(k.hi, k.lo, 0u, j, &r.hi, &r.lo); return r;
}
static inline uint32_t tf_bits32(TFKey k, uint32_t i) {
    uint32_t a, b; threefry2x32(k.hi, k.lo, 0u, i, &a, &b); return a ^ b;
}

static void compute_host_idx(int* h_idx) {
    const int n = HW;
    TFKey key42 = {0u, 42u};
    TFKey k1 = tf_child(key42, 0u);
    TFKey k2 = tf_child(key42, 1u);

    std::vector<int> order(n);
    for (int i = 0; i < n; i++) order[i] = i;
    {
        TFKey cur = k1;
        std::vector<uint64_t> kv(n);
        std::vector<int> nx(n);
        for (int round = 0; round < 2; round++) {
            TFKey nkey = tf_child(cur, 0u);
            TFKey sub  = tf_child(cur, 1u);
            for (int i = 0; i < n; i++)
                kv[(size_t)i] = ((uint64_t)tf_bits32(sub, (uint32_t)i) << 32) |
                                (uint32_t)i;
            std::sort(kv.begin(), kv.end());
            for (int j = 0; j < n; j++)
                nx[(size_t)j] = order[(size_t)(uint32_t)kv[(size_t)j]];
            order.swap(nx);
            cur = nkey;
        }
    }

    float p0 = (float)(1.0 - 0.3), pq = (float)(0.3 / 4.0);
    float c[5];
    c[0] = p0;
    for (int j = 1; j < 5; j++) c[j] = c[j - 1] + pq;

    std::vector<uint8_t> rs(n);
    for (int i = 0; i < n; i++) {
        uint32_t bits = tf_bits32(k2, (uint32_t)i);
        uint32_t fb = (bits >> 9) | 0x3F800000u;
        float f; std::memcpy(&f, &fb, 4);
        f -= 1.0f;
        float r = c[4] * (1.0f - f);
        int ind = 0;
        while (ind < 5 && c[ind] < r) ind++;
        rs[(size_t)i] = (uint8_t)ind;
    }

    for (int i = 0; i < n; i++) h_idx[i] = i;
    for (int t = 0; t < n; t++) {
        const int a = order[(size_t)t];
        const int r = rs[(size_t)t];
        const int i = a / GW, j = a % GW;
        const int ii = (r == 1) ? (i + 1) % GH : (r == 2) ? (i + GH - 1) % GH : i;
        const int jj = (r == 3) ? (j + 1) % GW : (r == 4) ? (j + GW - 1) % GW : j;
        const int b = (r == 0) ? a : (ii * GW + jj);
        const int va = h_idx[a], vb = h_idx[b];
        h_idx[a] = vb; h_idx[b] = va;
    }
}

// ---------------------------------------------------------------------------

extern "C" void kernel_launch(void* const* d_in, const int* in_sizes, int n_in,
                              void* d_out, int out_size) {
    (void)in_sizes; (void)n_in; (void)out_size;

    static int h_idx[HW];
    alignas(16) static unsigned short h_idxl[HW];   // ATS-read by copy kernel
    compute_host_idx(h_idx);

    // absolute in-plane uint16 indices (0..50175 fits uint16)
    for (int i = 0; i < HW; i++) {
        h_idxl[i] = (unsigned short)h_idx[i];
    }

    int ats = 0;
    cudaDeviceGetAttribute(&ats, cudaDevAttrPageableMemoryAccess, 0);

    if (ats) {
        write_idx_ats<<<(HW16 + 255) / 256, 256>>>(
            reinterpret_cast<const uint4*>(h_idxl));
    } else {
        cudaMemcpyToSymbolAsync(g_idxl, h_idxl, sizeof(h_idxl), 0,
                                cudaMemcpyHostToDevice, 0);
    }

    const float* x = (const float*)d_in[0];
    float* out = (float*)d_out;

    dim3 grid(HW4 / 256, NPLANES);   // (49, 384)
    clop_direct<<<grid, 256>>>(x, out);
}

// round 9
// speedup vs baseline: 1.1765x; 1.1765x over previous
#include <cuda_runtime.h>
#include <cstdint>
#include <cstring>
#include <vector>
#include <algorithm>

// ---------------------------------------------------------------------------
// CLOPLayer: out[b,c,i] = x[b,c,idx[i]], idx fixed (JAX threefry seed 42 +
// sequential neighbor-swap scan), recomputed bit-exact on the HOST each call.
//
// R9: SINGLE-KERNEL graph. The banded DMA gather (R7, best kernel) also
// delivers the idx table itself: the first 16 blocks each copy one chunk of
// the host-resident uint16 idx table into g_idxl via ATS (GB300 NVLink-C2C),
// fence, and set a flag; all blocks first issue their cp.async.bulk x-window
// fill (idx-independent) so the copy+spin hides under the DMA. This removes
// the separate writer node and its inter-node gaps (~6us of the R7 total).
// Replay-deterministic: the copy re-executes identically each launch and
// g_idxl content is bit-identical, so stale flags cannot change the output.
// ---------------------------------------------------------------------------

#define GH 224
#define GW 224
#define HW (GH * GW)          // 50176
#define HW4 (HW / 4)
#define NPLANES 384           // 128 * 3
#define BAND 56
#define NBANDS (GH / BAND)    // 4
#define BANDW (BAND * GW)     // 12544
#define BANDW4 (BANDW / 4)    // 3136
#define NT 512                // threads per gather block
#define GITER ((BANDW4 + NT - 1) / NT)   // 7
#define HW16 (HW / 8)         // 6272 uint4 units of the uint16 idx table
#define NCOPY 16              // copier blocks
#define CHUNK16 (HW16 / NCOPY)  // 392 uint4 per chunk

__device__ unsigned short g_idxl[HW];   // window-relative indices
__device__ unsigned int g_flag[NCOPY];  // zero-init; set once content is live

static __device__ __forceinline__ uint32_t smem_u32(const void* p) {
    uint32_t a;
    asm("{ .reg .u64 t; cvta.to.shared.u64 t, %1; cvt.u32.u64 %0, t; }"
        : "=r"(a) : "l"(p));
    return a;
}
static __device__ __forceinline__ void mbar_init(uint32_t mb, uint32_t cnt) {
    asm volatile("mbarrier.init.shared.b64 [%0], %1;" :: "r"(mb), "r"(cnt)
                 : "memory");
}
static __device__ __forceinline__ void mbar_expect_tx(uint32_t mb, uint32_t tx) {
    asm volatile("mbarrier.arrive.expect_tx.shared.b64 _, [%0], %1;"
                 :: "r"(mb), "r"(tx) : "memory");
}
static __device__ __forceinline__ void bulk_g2s(uint32_t dst, const void* src,
                                                uint32_t bytes, uint32_t mb) {
    asm volatile(
        "cp.async.bulk.shared::cluster.global.mbarrier::complete_tx::bytes "
        "[%0], [%1], %2, [%3];"
        :: "r"(dst), "l"(src), "r"(bytes), "r"(mb) : "memory");
}
static __device__ __forceinline__ void mbar_wait(uint32_t mb, uint32_t phase) {
    asm volatile(
        "{\n\t"
        ".reg .pred P;\n\t"
        "WAIT_%=: \n\t"
        "mbarrier.try_wait.parity.acquire.cta.shared::cta.b64 P, [%0], %1, 0x989680;\n\t"
        "@P bra.uni DONE_%=;\n\t"
        "bra.uni WAIT_%=;\n\t"
        "DONE_%=: \n\t"
        "}"
        :: "r"(mb), "r"(phase) : "memory");
}
static __device__ __forceinline__ unsigned int ld_acquire(unsigned int* p) {
    unsigned int v;
    asm volatile("ld.global.acquire.gpu.u32 %0, [%1];" : "=r"(v) : "l"(p)
                 : "memory");
    return v;
}

// ---- fused banded gather + idx delivery, compile-time window height Lc -----
template <int Lc>
__global__ __launch_bounds__(NT)
void clop_band_t(const float* __restrict__ x, float* __restrict__ out,
                 const uint4* __restrict__ hidx, int do_copy) {
    extern __shared__ float sp[];                 // Lc*GW floats, row-major
    __shared__ __align__(8) unsigned long long mbar_s;

    const int plane = blockIdx.x;
    const int band  = blockIdx.y;
    const float* src = x + (size_t)plane * HW;

    int ws = band * BAND - ((Lc - BAND) >> 1);    // toroidal window start row
    if (ws < 0) ws += GH;

    const uint32_t mb = smem_u32(&mbar_s);
    if (threadIdx.x == 0) mbar_init(mb, 1);
    __syncthreads();

    // (1) issue the x-window DMA first — independent of idx
    if (threadIdx.x == 0) {
        constexpr uint32_t TOTAL = (uint32_t)Lc * GW * sizeof(float);
        mbar_expect_tx(mb, TOTAL);
        const int n1 = (GH - ws < Lc) ? (GH - ws) : Lc;   // rows before wrap
        const uint32_t b1 = (uint32_t)n1 * GW * sizeof(float);
        bulk_g2s(smem_u32(sp), src + (size_t)ws * GW, b1, mb);
        if (n1 < Lc) {
            bulk_g2s(smem_u32(sp) + b1, src, TOTAL - b1, mb);
        }
    }

    // (2) copier role: first NCOPY scheduled blocks ship one idx chunk each
    if (do_copy) {
        const int bid = blockIdx.y * gridDim.x + blockIdx.x;  // x fastest
        if (bid < NCOPY) {
            const int base16 = bid * CHUNK16;
            if (threadIdx.x < CHUNK16) {
                reinterpret_cast<uint4*>(g_idxl)[base16 + threadIdx.x] =
                    __ldg(&hidx[base16 + threadIdx.x]);
            }
            __syncthreads();
            if (threadIdx.x == 0) {
                __threadfence();
                atomicExch(&g_flag[bid], 1u);
            }
        }
        // (3) wait until all chunks are live (skipped instantly on replays)
        if (threadIdx.x < NCOPY) {
            while (ld_acquire(&g_flag[threadIdx.x]) == 0u) __nanosleep(64);
        }
        __syncthreads();
    }

    // (4) prefetch idx for this band into registers (L2-hot), then DMA wait
    const size_t base = (size_t)band * BANDW;
    const ushort4* id4 = reinterpret_cast<const ushort4*>(g_idxl + base);
    ushort4 idbuf[GITER];
#pragma unroll
    for (int u = 0; u < GITER; u++) {
        const int k = threadIdx.x + u * NT;
        if (k < BANDW4) idbuf[u] = __ldg(&id4[k]);
    }

    mbar_wait(mb, 0);

    // (5) gather + coalesced float4 stores
    float4* dst = reinterpret_cast<float4*>(out + (size_t)plane * HW + base);
#pragma unroll
    for (int u = 0; u < GITER; u++) {
        const int k = threadIdx.x + u * NT;
        if (k < BANDW4) {
            const ushort4 id = idbuf[u];
            float4 v;
            v.x = sp[id.x];
            v.y = sp[id.y];
            v.z = sp[id.z];
            v.w = sp[id.w];
            __stcs(&dst[k], v);
        }
    }
}

// ---------------------------------------------------------------------------
// Host-side exact replication of the JAX RNG pipeline (partitionable threefry)
// ---------------------------------------------------------------------------

static inline uint32_t rotl32(uint32_t x, int d) {
    return (x << d) | (x >> (32 - d));
}

struct TFKey { uint32_t hi, lo; };

static void threefry2x32(uint32_t k0, uint32_t k1, uint32_t x0, uint32_t x1,
                         uint32_t* o0, uint32_t* o1) {
    const uint32_t ks0 = k0, ks1 = k1, ks2 = k0 ^ k1 ^ 0x1BD11BDAu;
    static const int ra[4] = {13, 15, 26, 6};
    static const int rb[4] = {17, 29, 16, 24};
    x0 += ks0; x1 += ks1;
    for (int i = 0; i < 4; i++) { x0 += x1; x1 = rotl32(x1, ra[i]); x1 ^= x0; }
    x0 += ks1; x1 += ks2 + 1u;
    for (int i = 0; i < 4; i++) { x0 += x1; x1 = rotl32(x1, rb[i]); x1 ^= x0; }
    x0 += ks2; x1 += ks0 + 2u;
    for (int i = 0; i < 4; i++) { x0 += x1; x1 = rotl32(x1, ra[i]); x1 ^= x0; }
    x0 += ks0; x1 += ks1 + 3u;
    for (int i = 0; i < 4; i++) { x0 += x1; x1 = rotl32(x1, rb[i]); x1 ^= x0; }
    x0 += ks1; x1 += ks2 + 4u;
    for (int i = 0; i < 4; i++) { x0 += x1; x1 = rotl32(x1, ra[i]); x1 ^= x0; }
    x0 += ks2; x1 += ks0 + 5u;
    *o0 = x0; *o1 = x1;
}

static inline TFKey tf_child(TFKey k, uint32_t j) {
    TFKey r; threefry2x32(k.hi, k.lo, 0u, j, &r.hi, &r.lo); return r;
}
static inline uint32_t tf_bits32(TFKey k, uint32_t i) {
    uint32_t a, b; threefry2x32(k.hi, k.lo, 0u, i, &a, &b); return a ^ b;
}

static void compute_host_idx(int* h_idx) {
    const int n = HW;
    TFKey key42 = {0u, 42u};
    TFKey k1 = tf_child(key42, 0u);
    TFKey k2 = tf_child(key42, 1u);

    std::vector<int> order(n);
    for (int i = 0; i < n; i++) order[i] = i;
    {
        TFKey cur = k1;
        std::vector<uint64_t> kv(n);
        std::vector<int> nx(n);
        for (int round = 0; round < 2; round++) {
            TFKey nkey = tf_child(cur, 0u);
            TFKey sub  = tf_child(cur, 1u);
            for (int i = 0; i < n; i++)
                kv[(size_t)i] = ((uint64_t)tf_bits32(sub, (uint32_t)i) << 32) |
                                (uint32_t)i;
            std::sort(kv.begin(), kv.end());
            for (int j = 0; j < n; j++)
                nx[(size_t)j] = order[(size_t)(uint32_t)kv[(size_t)j]];
            order.swap(nx);
            cur = nkey;
        }
    }

    float p0 = (float)(1.0 - 0.3), pq = (float)(0.3 / 4.0);
    float c[5];
    c[0] = p0;
    for (int j = 1; j < 5; j++) c[j] = c[j - 1] + pq;

    std::vector<uint8_t> rs(n);
    for (int i = 0; i < n; i++) {
        uint32_t bits = tf_bits32(k2, (uint32_t)i);
        uint32_t fb = (bits >> 9) | 0x3F800000u;
        float f; std::memcpy(&f, &fb, 4);
        f -= 1.0f;
        float r = c[4] * (1.0f - f);
        int ind = 0;
        while (ind < 5 && c[ind] < r) ind++;
        rs[(size_t)i] = (uint8_t)ind;
    }

    for (int i = 0; i < n; i++) h_idx[i] = i;
    for (int t = 0; t < n; t++) {
        const int a = order[(size_t)t];
        const int r = rs[(size_t)t];
        const int i = a / GW, j = a % GW;
        const int ii = (r == 1) ? (i + 1) % GH : (r == 2) ? (i + GH - 1) % GH : i;
        const int jj = (r == 3) ? (j + 1) % GW : (r == 4) ? (j + GW - 1) % GW : j;
        const int b = (r == 0) ? a : (ii * GW + jj);
        const int va = h_idx[a], vb = h_idx[b];
        h_idx[a] = vb; h_idx[b] = va;
    }
}

// ---------------------------------------------------------------------------

template <int Lc>
static void launch_band(const float* x, float* out, const uint4* hidx,
                        int do_copy) {
    const int smem = Lc * GW * (int)sizeof(float);
    cudaFuncSetAttribute(clop_band_t<Lc>,
                         cudaFuncAttributeMaxDynamicSharedMemorySize, smem);
    dim3 grid(NPLANES, NBANDS);
    clop_band_t<Lc><<<grid, NT, smem>>>(x, out, hidx, do_copy);
}

extern "C" void kernel_launch(void* const* d_in, const int* in_sizes, int n_in,
                              void* d_out, int out_size) {
    (void)in_sizes; (void)n_in; (void)out_size;

    static int h_idx[HW];
    alignas(16) static unsigned short h_idxl[HW];   // ATS-read by the kernel
    compute_host_idx(h_idx);

    // max toroidal row distance from each output row's band window
    int D = 0;
    for (int i = 0; i < HW; i++) {
        const int r_out = i / GW;
        const int bandstart = (r_out / BAND) * BAND;
        const int r_src = h_idx[i] / GW;
        int dist = 0;
        if (r_src >= bandstart && r_src < bandstart + BAND) {
            dist = 0;
        } else {
            int dlo = (bandstart - r_src + GH) % GH;
            int dhi = (r_src - (bandstart + BAND - 1) + GH) % GH;
            dist = dlo < dhi ? dlo : dhi;
        }
        if (dist > D) D = dist;
    }

    // compile-time window heights: L = BAND + 2*Dp, padded up
    int Lc;
    if (D <= 2)       Lc = 60;
    else if (D <= 6)  Lc = 68;
    else if (D <= 10) Lc = 76;
    else if (D <= 18) Lc = 92;
    else              Lc = 224;   // degenerate: whole plane (window = plane)

    // window-relative row-major indices for the padded window
    const int Dp = (Lc - BAND) / 2;
    for (int i = 0; i < HW; i++) {
        const int r_out = i / GW;
        const int ws0 = (r_out / BAND) * BAND - Dp;
        const int r_src = h_idx[i] / GW;
        const int c_src = h_idx[i] % GW;
        int t = r_src - ws0;
        t %= GH; if (t < 0) t += GH;
        h_idxl[i] = (unsigned short)(t * GW + c_src);
    }

    int ats = 0;
    cudaDeviceGetAttribute(&ats, cudaDevAttrPageableMemoryAccess, 0);

    const float* x = (const float*)d_in[0];
    float* out = (float*)d_out;
    const uint4* hidx = reinterpret_cast<const uint4*>(h_idxl);

    if (!ats) {
        // fallback: explicit memcpy node, kernel skips copy+spin
        cudaMemcpyToSymbolAsync(g_idxl, h_idxl, sizeof(h_idxl), 0,
                                cudaMemcpyHostToDevice, 0);
    }
    const int do_copy = ats ? 1 : 0;

    if (Lc == 60)      launch_band<60>(x, out, hidx, do_copy);
    else if (Lc == 68) launch_band<68>(x, out, hidx, do_copy);
    else if (Lc == 76) launch_band<76>(x, out, hidx, do_copy);
    else if (Lc == 92) launch_band<92>(x, out, hidx, do_copy);
    else               launch_band<224>(x, out, hidx, do_copy);
}